// round 14
// baseline (speedup 1.0000x reference)
#include <cuda_runtime.h>
#include <cuda_fp16.h>
#include <cstdint>

// PatchEmbed round 14: R13 (512 threads, 4 warps/SMSP, halved n-strips) with
// the layer1 ownership bug fixed: layer1 reverted to 1-thread-per-row
// (thread tid<256 owns gather AND layer1 for row tid, as in R12).
// Numerics: fp16 m16n8k16, f32 accumulate.

constexpr int Bb = 8, Nn = 16384, Mc = 2048, Kn = 32;
constexpr int C1 = 64, C2 = 128, C3 = 256;
constexpr int P  = 8;                        // points/group -> M = 256 rows
constexpr int NGRP = Bb * Mc / P;            // 2048
constexpr int GRID = 152;
constexpr int THREADS = 512;
constexpr int MROWS = P * Kn;                // 256

constexpr int S1W = 36;                      // h1 row stride in 32-bit words
constexpr int S2W = 68;                      // h2 row stride in words
constexpr int S1B = S1W * 4;                 // 144 B
constexpr int S2B = S2W * 4;                 // 272 B
constexpr int H1W = MROWS * S1W;
constexpr int H2W = MROWS * S2W;
constexpr uint32_t SMEM_BYTES = (H1W + H2W) * 4;   // 106496 B

__device__ __forceinline__ uint32_t packh2(float lo, float hi) {
    __half2 h = __floats2half2_rn(lo, hi);
    return *reinterpret_cast<uint32_t*>(&h);
}

__device__ __forceinline__ uint32_t smem_u32(const void* p) {
    uint32_t a;
    asm("{ .reg .u64 t; cvta.to.shared.u64 t, %1; cvt.u32.u64 %0, t; }" : "=r"(a) : "l"(p));
    return a;
}

__device__ __forceinline__ void ldsm4(uint4& v, uint32_t addr) {
    asm volatile("ldmatrix.sync.aligned.m8n8.x4.shared.b16 {%0,%1,%2,%3}, [%4];"
                 : "=r"(v.x), "=r"(v.y), "=r"(v.z), "=r"(v.w) : "r"(addr));
}

__device__ __forceinline__ void mma16(float& d0, float& d1, float& d2, float& d3,
                                      uint32_t a0, uint32_t a1, uint32_t a2, uint32_t a3,
                                      uint32_t b0, uint32_t b1) {
    asm volatile(
        "mma.sync.aligned.m16n8k16.row.col.f32.f16.f16.f32 "
        "{%0,%1,%2,%3},{%4,%5,%6,%7},{%8,%9},{%0,%1,%2,%3};"
        : "+f"(d0), "+f"(d1), "+f"(d2), "+f"(d3)
        : "r"(a0), "r"(a1), "r"(a2), "r"(a3), "r"(b0), "r"(b1));
}

__global__ __launch_bounds__(THREADS, 1)
void pe_mma(const float* __restrict__ xyz,
            const float* __restrict__ centers,
            const int*   __restrict__ idx,
            const float* __restrict__ W1, const float* __restrict__ b1,
            const float* __restrict__ W2, const float* __restrict__ b2,
            const float* __restrict__ W3, const float* __restrict__ b3,
            float* __restrict__ out) {
    extern __shared__ uint32_t smw[];
    uint32_t* h1u = smw;                     // [256][S1W] f16x2
    uint32_t* h2u = smw + H1W;               // [256][S2W]

    __shared__ float4 wb1[64];               // {w0,w1,w2,bias}

    const int tid  = threadIdx.x;
    const int warp = tid >> 5;               // 0..15
    const int lane = tid & 31;
    const int g    = lane >> 2;
    const int t    = lane & 3;

    const uint32_t h1a = smem_u32(h1u);
    const uint32_t h2a = smem_u32(h2u);
    const uint32_t lm1 = h1a + (uint32_t)(lane & 15) * S1B + (uint32_t)(lane >> 4) * 16;
    const uint32_t lm2 = h2a + (uint32_t)(lane & 15) * S2B + (uint32_t)(lane >> 4) * 16;

    // ---- one-time: W1/b1 table ----
    if (tid < 64)
        wb1[tid] = make_float4(__ldg(&W1[tid * 3 + 0]), __ldg(&W1[tid * 3 + 1]),
                               __ldg(&W1[tid * 3 + 2]), __ldg(&b1[tid]));

    // ---- one-time: resident f16 weight B-fragments ----
    const int c2b = warp * 8;                // GEMM2 n-strip: 8 channels
    uint32_t b2f[4][2];
#pragma unroll
    for (int kc = 0; kc < 4; kc++) {
        const int row = c2b + g;
        const float* wr = W2 + (size_t)row * C1 + kc * 16;
        b2f[kc][0] = packh2(__ldg(wr + 2 * t),     __ldg(wr + 2 * t + 1));
        b2f[kc][1] = packh2(__ldg(wr + 2 * t + 8), __ldg(wr + 2 * t + 9));
    }
    const int chb = warp * 16;               // GEMM3 n-strip: 16 channels
    uint32_t b3f[8][2][2];
#pragma unroll
    for (int kc = 0; kc < 8; kc++)
#pragma unroll
        for (int n = 0; n < 2; n++) {
            const int row = chb + n * 8 + g;
            const float* wr = W3 + (size_t)row * C2 + kc * 16;
            b3f[kc][n][0] = packh2(__ldg(wr + 2 * t),     __ldg(wr + 2 * t + 1));
            b3f[kc][n][1] = packh2(__ldg(wr + 2 * t + 8), __ldg(wr + 2 * t + 9));
        }
    const float bias2a = __ldg(&b2[c2b + 2 * t]);
    const float bias2b = __ldg(&b2[c2b + 2 * t + 1]);
    float b3r[2][2];
#pragma unroll
    for (int n = 0; n < 2; n++) {
        const int ch = chb + n * 8 + 2 * (lane & 3);
        b3r[n][0] = __ldg(&b3[ch]);
        b3r[n][1] = __ldg(&b3[ch + 1]);
    }

    __syncthreads();                         // wb1 visible before any layer1

    auto gather = [&](int grp, float& lx, float& ly, float& lz) {
        const int bm0 = grp * P;
        const int b   = bm0 >> 11;
        const int bm  = bm0 + (tid >> 5);    // tid < 256: p = tid>>5
        const int id  = __ldg(&idx[(size_t)bm * Kn + (tid & 31)]);
        const float* xp = xyz + ((size_t)b * Nn + id) * 3;
        const float* cp = centers + (size_t)bm * 3;
        lx = __ldg(xp + 0) - __ldg(cp + 0);
        ly = __ldg(xp + 1) - __ldg(cp + 1);
        lz = __ldg(xp + 2) - __ldg(cp + 2);
    };
    // layer1: thread tid (<256) owns row tid — full 64 channels (R12-proven)
    auto layer1 = [&](float lx, float ly, float lz) {
        uint32_t* ph = h1u + tid * S1W;
#pragma unroll
        for (int j4 = 0; j4 < 8; j4++) {
            uint4 o;
#pragma unroll
            for (int w = 0; w < 4; w++) {
                const int c0 = j4 * 8 + 2 * w;
                const float4 wa = wb1[c0];
                const float4 wb = wb1[c0 + 1];
                const float vlo = fmaxf(fmaf(wa.x, lx, fmaf(wa.y, ly, fmaf(wa.z, lz, wa.w))), 0.f);
                const float vhi = fmaxf(fmaf(wb.x, lx, fmaf(wb.y, ly, fmaf(wb.z, lz, wb.w))), 0.f);
                (&o.x)[w] = packh2(vlo, vhi);
            }
            *reinterpret_cast<uint4*>(ph + j4 * 4) = o;
        }
    };

    // ---- prologue ----
    int grp = blockIdx.x;
    if (grp < NGRP && tid < 256) {
        float lx, ly, lz;
        gather(grp, lx, ly, lz);
        layer1(lx, ly, lz);
    }
    __syncthreads();

    // ---- persistent group loop ----
    for (; grp < NGRP; grp += GRID) {
        const int bm0 = grp * P;

        float nlx = 0.f, nly = 0.f, nlz = 0.f;
        if (tid < 256) {
            int gn = grp + GRID;
            if (gn >= NGRP) gn = NGRP - 1;
            gather(gn, nlx, nly, nlz);
        }

        // -- GEMM2: 4 passes of M=64; 16 pipelined (mt,kc) steps, 1 mma each --
#pragma unroll 1
        for (int pass = 0; pass < 4; pass++) {
            const uint32_t base = lm1 + (uint32_t)(pass * 64) * S1B;
            float acc[4][4];
#pragma unroll
            for (int mt = 0; mt < 4; mt++)
#pragma unroll
                for (int i = 0; i < 4; i++) acc[mt][i] = 0.f;

            uint4 fr[2];
            ldsm4(fr[0], base);
#pragma unroll
            for (int s = 0; s < 16; s++) {
                const int mt = s >> 2, kc = s & 3;
                if (s + 1 < 16) {
                    const int s1 = s + 1;
                    ldsm4(fr[s1 & 1], base + (uint32_t)((s1 >> 2) * 16 * S1B + (s1 & 3) * 32));
                }
                const uint4 a = fr[s & 1];
                mma16(acc[mt][0], acc[mt][1], acc[mt][2], acc[mt][3],
                      a.x, a.y, a.z, a.w, b2f[kc][0], b2f[kc][1]);
            }
            // epi2: +bias, relu, pack, store 8 cols (word col = warp*4 + t)
#pragma unroll
            for (int mt = 0; mt < 4; mt++) {
                const int r0 = pass * 64 + mt * 16 + g;
                const int wcol = warp * 4 + t;
                h2u[r0 * S2W + wcol] =
                    packh2(fmaxf(acc[mt][0] + bias2a, 0.f),
                           fmaxf(acc[mt][1] + bias2b, 0.f));
                h2u[(r0 + 8) * S2W + wcol] =
                    packh2(fmaxf(acc[mt][2] + bias2a, 0.f),
                           fmaxf(acc[mt][3] + bias2b, 0.f));
            }
        }
        __syncthreads();

        // -- GEMM3 + max epilogue: per p, 16 pipelined steps, 2 mma each --
#pragma unroll 1
        for (int p = 0; p < P; p++) {
            const uint32_t base = lm2 + (uint32_t)(p * 32) * S2B;
            float acc[2][2][4];
#pragma unroll
            for (int h = 0; h < 2; h++)
#pragma unroll
                for (int n = 0; n < 2; n++)
#pragma unroll
                    for (int i = 0; i < 4; i++) acc[h][n][i] = 0.f;

            uint4 fr[2];
            ldsm4(fr[0], base);
#pragma unroll
            for (int s = 0; s < 16; s++) {
                const int hmt = s >> 3, kc = s & 7;
                if (s + 1 < 16) {
                    const int s1 = s + 1;
                    ldsm4(fr[s1 & 1], base + (uint32_t)((s1 >> 3) * 16 * S2B + (s1 & 7) * 32));
                }
                const uint4 a = fr[s & 1];
#pragma unroll
                for (int n = 0; n < 2; n++)
                    mma16(acc[hmt][n][0], acc[hmt][n][1], acc[hmt][n][2], acc[hmt][n][3],
                          a.x, a.y, a.z, a.w, b3f[kc][n][0], b3f[kc][n][1]);
            }

#pragma unroll
            for (int n = 0; n < 2; n++) {
                float ve = fmaxf(fmaxf(acc[0][n][0], acc[0][n][2]),
                                 fmaxf(acc[1][n][0], acc[1][n][2]));
                float vo = fmaxf(fmaxf(acc[0][n][1], acc[0][n][3]),
                                 fmaxf(acc[1][n][1], acc[1][n][3]));
#pragma unroll
                for (int s = 4; s < 32; s <<= 1) {
                    ve = fmaxf(ve, __shfl_xor_sync(0xffffffffu, ve, s));
                    vo = fmaxf(vo, __shfl_xor_sync(0xffffffffu, vo, s));
                }
                if (lane < 4) {
                    const int ch = chb + n * 8 + 2 * lane;
                    float2 o = {ve + b3r[n][0], vo + b3r[n][1]};
                    *reinterpret_cast<float2*>(out + (size_t)(bm0 + p) * C3 + ch) = o;
                }
            }
        }

        // -- layer1 for next group (threads 0..255 own their rows) --
        if (tid < 256) layer1(nlx, nly, nlz);
        __syncthreads();
    }
}

extern "C" void kernel_launch(void* const* d_in, const int* in_sizes, int n_in,
                              void* d_out, int out_size) {
    (void)in_sizes; (void)n_in; (void)out_size;
    const float* xyz     = (const float*)d_in[0];
    const float* centers = (const float*)d_in[1];
    const int*   idx     = (const int*)  d_in[2];
    const float* W1      = (const float*)d_in[3];
    const float* b1      = (const float*)d_in[4];
    const float* W2      = (const float*)d_in[5];
    const float* b2      = (const float*)d_in[6];
    const float* W3      = (const float*)d_in[7];
    const float* b3      = (const float*)d_in[8];
    float*       out     = (float*)d_out;

    cudaFuncSetAttribute(pe_mma, cudaFuncAttributeMaxDynamicSharedMemorySize, SMEM_BYTES);
    pe_mma<<<GRID, THREADS, SMEM_BYTES>>>(xyz, centers, idx,
                                          W1, b1, W2, b2, W3, b3, out);
}

// round 15
// speedup vs baseline: 1.4414x; 1.4414x over previous
#include <cuda_runtime.h>
#include <cuda_fp16.h>
#include <cstdint>

// PatchEmbed round 15: 512 threads (4 warps/SMSP) with A-redundancy held at
// R12 levels: GEMM2 split 8 n-strips x 2 m-halves; GEMM3 split 8 n-strips
// (32ch) x 2 k-halves with f32 partial-sum exchange through smem + named
// pair barriers. fp16 m16n8k16, f32 accumulate.

constexpr int Bb = 8, Nn = 16384, Mc = 2048, Kn = 32;
constexpr int C1 = 64, C2 = 128, C3 = 256;
constexpr int P  = 8;                        // points/group -> M = 256 rows
constexpr int NGRP = Bb * Mc / P;            // 2048
constexpr int GRID = 152;
constexpr int THREADS = 512;
constexpr int MROWS = P * Kn;                // 256

constexpr int S1W = 36;                      // h1 row stride in 32-bit words
constexpr int S2W = 68;                      // h2 row stride in words
constexpr int S1B = S1W * 4;                 // 144 B
constexpr int S2B = S2W * 4;                 // 272 B
constexpr int H1W = MROWS * S1W;             // 9216 words
constexpr int H2W = MROWS * S2W;             // 17408 words
// psum: 8 pairs x 2 parity x (8 j4 x 32 lanes x 16B) = 64 KB
constexpr int PS_W = 8 * 2 * 8 * 32 * 4;     // 16384 words
constexpr uint32_t SMEM_BYTES = (H1W + H2W + PS_W) * 4;   // 172032 B

__device__ __forceinline__ uint32_t packh2(float lo, float hi) {
    __half2 h = __floats2half2_rn(lo, hi);
    return *reinterpret_cast<uint32_t*>(&h);
}

__device__ __forceinline__ uint32_t smem_u32(const void* p) {
    uint32_t a;
    asm("{ .reg .u64 t; cvta.to.shared.u64 t, %1; cvt.u32.u64 %0, t; }" : "=r"(a) : "l"(p));
    return a;
}

__device__ __forceinline__ void ldsm4(uint4& v, uint32_t addr) {
    asm volatile("ldmatrix.sync.aligned.m8n8.x4.shared.b16 {%0,%1,%2,%3}, [%4];"
                 : "=r"(v.x), "=r"(v.y), "=r"(v.z), "=r"(v.w) : "r"(addr));
}

__device__ __forceinline__ void mma16(float& d0, float& d1, float& d2, float& d3,
                                      uint32_t a0, uint32_t a1, uint32_t a2, uint32_t a3,
                                      uint32_t b0, uint32_t b1) {
    asm volatile(
        "mma.sync.aligned.m16n8k16.row.col.f32.f16.f16.f32 "
        "{%0,%1,%2,%3},{%4,%5,%6,%7},{%8,%9},{%0,%1,%2,%3};"
        : "+f"(d0), "+f"(d1), "+f"(d2), "+f"(d3)
        : "r"(a0), "r"(a1), "r"(a2), "r"(a3), "r"(b0), "r"(b1));
}

__global__ __launch_bounds__(THREADS, 1)
void pe_mma(const float* __restrict__ xyz,
            const float* __restrict__ centers,
            const int*   __restrict__ idx,
            const float* __restrict__ W1, const float* __restrict__ b1,
            const float* __restrict__ W2, const float* __restrict__ b2,
            const float* __restrict__ W3, const float* __restrict__ b3,
            float* __restrict__ out) {
    extern __shared__ uint32_t smw[];
    uint32_t* h1u = smw;                     // [256][S1W]
    uint32_t* h2u = smw + H1W;               // [256][S2W]
    uint32_t* psw = smw + H1W + H2W;         // partial-sum exchange

    __shared__ float4 wb1[64];               // {w0,w1,w2,bias}

    const int tid  = threadIdx.x;
    const int warp = tid >> 5;               // 0..15
    const int lane = tid & 31;
    const int g    = lane >> 2;
    const int t    = lane & 3;
    const int nst  = warp & 7;               // n-strip id (pair id)
    const int kh   = warp >> 3;              // GEMM3 k-half / GEMM2 m-half

    const uint32_t h1a = smem_u32(h1u);
    const uint32_t h2a = smem_u32(h2u);
    const uint32_t psa = smem_u32(psw);
    const uint32_t lm1 = h1a + (uint32_t)(lane & 15) * S1B + (uint32_t)(lane >> 4) * 16;
    // GEMM3 ldsm base includes the warp's k-half byte offset (kh * 64k * 2B)
    const uint32_t lm2 = h2a + (uint32_t)(lane & 15) * S2B + (uint32_t)(lane >> 4) * 16
                             + (uint32_t)kh * 128;

    // ---- one-time: W1/b1 table ----
    if (tid < 64)
        wb1[tid] = make_float4(__ldg(&W1[tid * 3 + 0]), __ldg(&W1[tid * 3 + 1]),
                               __ldg(&W1[tid * 3 + 2]), __ldg(&b1[tid]));

    // ---- one-time: resident f16 weight B-fragments ----
    const int c2b = nst * 16;                // GEMM2 strip: 16 c2
    uint32_t b2f[4][2][2];
#pragma unroll
    for (int kc = 0; kc < 4; kc++)
#pragma unroll
        for (int n = 0; n < 2; n++) {
            const int row = c2b + n * 8 + g;
            const float* wr = W2 + (size_t)row * C1 + kc * 16;
            b2f[kc][n][0] = packh2(__ldg(wr + 2 * t),     __ldg(wr + 2 * t + 1));
            b2f[kc][n][1] = packh2(__ldg(wr + 2 * t + 8), __ldg(wr + 2 * t + 9));
        }
    const int chb = nst * 32;                // GEMM3 strip: 32 ch (k-half per warp)
    uint32_t b3f[4][4][2];
#pragma unroll
    for (int kc = 0; kc < 4; kc++)
#pragma unroll
        for (int n = 0; n < 4; n++) {
            const int row = chb + n * 8 + g;
            const float* wr = W3 + (size_t)row * C2 + kh * 64 + kc * 16;
            b3f[kc][n][0] = packh2(__ldg(wr + 2 * t),     __ldg(wr + 2 * t + 1));
            b3f[kc][n][1] = packh2(__ldg(wr + 2 * t + 8), __ldg(wr + 2 * t + 9));
        }
    const float bias2a = __ldg(&b2[c2b + 2 * t]);
    const float bias2b = __ldg(&b2[c2b + 2 * t + 1]);
    float b3r[4][2];
#pragma unroll
    for (int n = 0; n < 4; n++) {
        const int ch = chb + n * 8 + 2 * (lane & 3);
        b3r[n][0] = __ldg(&b3[ch]);
        b3r[n][1] = __ldg(&b3[ch + 1]);
    }

    __syncthreads();                         // wb1 visible before any layer1

    auto gather = [&](int grp, float& lx, float& ly, float& lz) {
        const int bm0 = grp * P;
        const int b   = bm0 >> 11;
        const int bm  = bm0 + (tid >> 5);    // tid < 256
        const int id  = __ldg(&idx[(size_t)bm * Kn + (tid & 31)]);
        const float* xp = xyz + ((size_t)b * Nn + id) * 3;
        const float* cp = centers + (size_t)bm * 3;
        lx = __ldg(xp + 0) - __ldg(cp + 0);
        ly = __ldg(xp + 1) - __ldg(cp + 1);
        lz = __ldg(xp + 2) - __ldg(cp + 2);
    };
    // layer1: thread tid (<256) owns row tid (R12-proven ownership)
    auto layer1 = [&](float lx, float ly, float lz) {
        uint32_t* ph = h1u + tid * S1W;
#pragma unroll
        for (int j4 = 0; j4 < 8; j4++) {
            uint4 o;
#pragma unroll
            for (int w = 0; w < 4; w++) {
                const int c0 = j4 * 8 + 2 * w;
                const float4 wa = wb1[c0];
                const float4 wb = wb1[c0 + 1];
                const float vlo = fmaxf(fmaf(wa.x, lx, fmaf(wa.y, ly, fmaf(wa.z, lz, wa.w))), 0.f);
                const float vhi = fmaxf(fmaf(wb.x, lx, fmaf(wb.y, ly, fmaf(wb.z, lz, wb.w))), 0.f);
                (&o.x)[w] = packh2(vlo, vhi);
            }
            *reinterpret_cast<uint4*>(ph + j4 * 4) = o;
        }
    };

    // ---- prologue ----
    int grp = blockIdx.x;
    if (grp < NGRP && tid < 256) {
        float lx, ly, lz;
        gather(grp, lx, ly, lz);
        layer1(lx, ly, lz);
    }
    __syncthreads();

    // ---- persistent group loop ----
    for (; grp < NGRP; grp += GRID) {
        const int bm0 = grp * P;

        float nlx = 0.f, nly = 0.f, nlz = 0.f;
        if (tid < 256) {
            int gn = grp + GRID;
            if (gn >= NGRP) gn = NGRP - 1;
            gather(gn, nlx, nly, nlz);
        }

        // -- GEMM2: warp does its m-half = 2 passes of 64 rows --
#pragma unroll 1
        for (int pp = 0; pp < 2; pp++) {
            const int pass = kh * 2 + pp;
            const uint32_t base = lm1 + (uint32_t)(pass * 64) * S1B;
            float acc[4][2][4];
#pragma unroll
            for (int mt = 0; mt < 4; mt++)
#pragma unroll
                for (int n = 0; n < 2; n++)
#pragma unroll
                    for (int i = 0; i < 4; i++) acc[mt][n][i] = 0.f;

            uint4 fr[2];
            ldsm4(fr[0], base);
#pragma unroll
            for (int s = 0; s < 16; s++) {
                const int mt = s >> 2, kc = s & 3;
                if (s + 1 < 16) {
                    const int s1 = s + 1;
                    ldsm4(fr[s1 & 1], base + (uint32_t)((s1 >> 2) * 16 * S1B + (s1 & 3) * 32));
                }
                const uint4 a = fr[s & 1];
#pragma unroll
                for (int n = 0; n < 2; n++)
                    mma16(acc[mt][n][0], acc[mt][n][1], acc[mt][n][2], acc[mt][n][3],
                          a.x, a.y, a.z, a.w, b2f[kc][n][0], b2f[kc][n][1]);
            }
            // epi2: +bias, relu, pack, store (word cols nst*8 + n*4 + t)
#pragma unroll
            for (int mt = 0; mt < 4; mt++) {
                const int r0 = pass * 64 + mt * 16 + g;
#pragma unroll
                for (int n = 0; n < 2; n++) {
                    const int wcol = nst * 8 + n * 4 + t;
                    h2u[r0 * S2W + wcol] =
                        packh2(fmaxf(acc[mt][n][0] + bias2a, 0.f),
                               fmaxf(acc[mt][n][1] + bias2b, 0.f));
                    h2u[(r0 + 8) * S2W + wcol] =
                        packh2(fmaxf(acc[mt][n][2] + bias2a, 0.f),
                               fmaxf(acc[mt][n][3] + bias2b, 0.f));
                }
            }
        }
        __syncthreads();

        // -- GEMM3: per p, warp computes its k-half over 32 ch; pair-exchange --
#pragma unroll 1
        for (int p = 0; p < P; p++) {
            const uint32_t base = lm2 + (uint32_t)(p * 32) * S2B;
            float acc[2][4][4];
#pragma unroll
            for (int h = 0; h < 2; h++)
#pragma unroll
                for (int n = 0; n < 4; n++)
#pragma unroll
                    for (int i = 0; i < 4; i++) acc[h][n][i] = 0.f;

            uint4 fr[2];
            ldsm4(fr[0], base);
#pragma unroll
            for (int s = 0; s < 8; s++) {       // 2 hmt x 4 kc (this k-half)
                const int hmt = s >> 2, kc = s & 3;
                if (s + 1 < 8) {
                    const int s1 = s + 1;
                    ldsm4(fr[s1 & 1], base + (uint32_t)((s1 >> 2) * 16 * S2B + (s1 & 3) * 32));
                }
                const uint4 a = fr[s & 1];
#pragma unroll
                for (int n = 0; n < 4; n++)
                    mma16(acc[hmt][n][0], acc[hmt][n][1], acc[hmt][n][2], acc[hmt][n][3],
                          a.x, a.y, a.z, a.w, b3f[kc][n][0], b3f[kc][n][1]);
            }

            // pair exchange: writer = warp with kh == (p&1); reader sums+reduces
            const int par = p & 1;
            const uint32_t blk = psa + (uint32_t)(nst * 2 + par) * 4096;
            const bool writer = (kh == par);
            if (writer) {
#pragma unroll
                for (int h = 0; h < 2; h++)
#pragma unroll
                    for (int n = 0; n < 4; n++) {
                        const int j4 = h * 4 + n;
                        uint4 v;
                        v.x = __float_as_uint(acc[h][n][0]);
                        v.y = __float_as_uint(acc[h][n][1]);
                        v.z = __float_as_uint(acc[h][n][2]);
                        v.w = __float_as_uint(acc[h][n][3]);
                        *reinterpret_cast<uint4*>(
                            reinterpret_cast<char*>(psw) + (blk - psa) + (j4 * 32 + lane) * 16) = v;
                    }
            }
            asm volatile("bar.sync %0, %1;" :: "r"(nst + 1), "r"(64) : "memory");
            if (!writer) {
#pragma unroll
                for (int h = 0; h < 2; h++)
#pragma unroll
                    for (int n = 0; n < 4; n++) {
                        const int j4 = h * 4 + n;
                        const uint4 v = *reinterpret_cast<const uint4*>(
                            reinterpret_cast<const char*>(psw) + (blk - psa) + (j4 * 32 + lane) * 16);
                        acc[h][n][0] += __uint_as_float(v.x);
                        acc[h][n][1] += __uint_as_float(v.y);
                        acc[h][n][2] += __uint_as_float(v.z);
                        acc[h][n][3] += __uint_as_float(v.w);
                    }
#pragma unroll
                for (int n = 0; n < 4; n++) {
                    float ve = fmaxf(fmaxf(acc[0][n][0], acc[0][n][2]),
                                     fmaxf(acc[1][n][0], acc[1][n][2]));
                    float vo = fmaxf(fmaxf(acc[0][n][1], acc[0][n][3]),
                                     fmaxf(acc[1][n][1], acc[1][n][3]));
#pragma unroll
                    for (int s = 4; s < 32; s <<= 1) {
                        ve = fmaxf(ve, __shfl_xor_sync(0xffffffffu, ve, s));
                        vo = fmaxf(vo, __shfl_xor_sync(0xffffffffu, vo, s));
                    }
                    if (lane < 4) {
                        const int ch = chb + n * 8 + 2 * lane;
                        float2 o = {ve + b3r[n][0], vo + b3r[n][1]};
                        *reinterpret_cast<float2*>(out + (size_t)(bm0 + p) * C3 + ch) = o;
                    }
                }
            }
        }

        // -- layer1 for next group --
        if (tid < 256) layer1(nlx, nly, nlz);
        __syncthreads();
    }
}

extern "C" void kernel_launch(void* const* d_in, const int* in_sizes, int n_in,
                              void* d_out, int out_size) {
    (void)in_sizes; (void)n_in; (void)out_size;
    const float* xyz     = (const float*)d_in[0];
    const float* centers = (const float*)d_in[1];
    const int*   idx     = (const int*)  d_in[2];
    const float* W1      = (const float*)d_in[3];
    const float* b1      = (const float*)d_in[4];
    const float* W2      = (const float*)d_in[5];
    const float* b2      = (const float*)d_in[6];
    const float* W3      = (const float*)d_in[7];
    const float* b3      = (const float*)d_in[8];
    float*       out     = (float*)d_out;

    cudaFuncSetAttribute(pe_mma, cudaFuncAttributeMaxDynamicSharedMemorySize, SMEM_BYTES);
    pe_mma<<<GRID, THREADS, SMEM_BYTES>>>(xyz, centers, idx,
                                          W1, b1, W2, b2, W3, b3, out);
}

// round 17
// speedup vs baseline: 1.7721x; 1.2294x over previous
#include <cuda_runtime.h>
#include <cuda_fp16.h>
#include <cstdint>

// PatchEmbed round 16: R12 structure with TWO co-resident CTAs per SM
// (__launch_bounds__(256,2), grid 304). Independent per-CTA barriers let one
// CTA's GEMM fill the other's barrier/epilogue gaps (R15 diagnosis: tensor
// pipe only ~46% occupied, nothing saturated => phase-serialization bound).
// b2f loaded per-group (dead during GEMM3) to lower the register peak.
// Numerics: fp16 m16n8k16, f32 accumulate (rel_err 3.55e-4).

constexpr int Bb = 8, Nn = 16384, Mc = 2048, Kn = 32;
constexpr int C1 = 64, C2 = 128, C3 = 256;
constexpr int P  = 8;                        // points/group -> M = 256 rows
constexpr int NGRP = Bb * Mc / P;            // 2048
constexpr int GRID = 304;                    // 2 CTAs per SM, persistent
constexpr int THREADS = 256;
constexpr int MROWS = P * Kn;                // 256

constexpr int S1W = 36;                      // h1 row stride in 32-bit words
constexpr int S2W = 68;                      // h2 row stride in words
constexpr int S1B = S1W * 4;                 // 144 B
constexpr int S2B = S2W * 4;                 // 272 B
constexpr int H1W = MROWS * S1W;
constexpr int H2W = MROWS * S2W;
constexpr uint32_t SMEM_BYTES = (H1W + H2W) * 4;   // 106496 B (x2 = 213KB/SM)

__device__ __forceinline__ uint32_t packh2(float lo, float hi) {
    __half2 h = __floats2half2_rn(lo, hi);
    return *reinterpret_cast<uint32_t*>(&h);
}

__device__ __forceinline__ uint32_t smem_u32(const void* p) {
    uint32_t a;
    asm("{ .reg .u64 t; cvta.to.shared.u64 t, %1; cvt.u32.u64 %0, t; }" : "=r"(a) : "l"(p));
    return a;
}

__device__ __forceinline__ void ldsm4(uint4& v, uint32_t addr) {
    asm volatile("ldmatrix.sync.aligned.m8n8.x4.shared.b16 {%0,%1,%2,%3}, [%4];"
                 : "=r"(v.x), "=r"(v.y), "=r"(v.z), "=r"(v.w) : "r"(addr));
}

__device__ __forceinline__ void mma16(float& d0, float& d1, float& d2, float& d3,
                                      uint32_t a0, uint32_t a1, uint32_t a2, uint32_t a3,
                                      uint32_t b0, uint32_t b1) {
    asm volatile(
        "mma.sync.aligned.m16n8k16.row.col.f32.f16.f16.f32 "
        "{%0,%1,%2,%3},{%4,%5,%6,%7},{%8,%9},{%0,%1,%2,%3};"
        : "+f"(d0), "+f"(d1), "+f"(d2), "+f"(d3)
        : "r"(a0), "r"(a1), "r"(a2), "r"(a3), "r"(b0), "r"(b1));
}

__global__ __launch_bounds__(THREADS, 2)
void pe_mma(const float* __restrict__ xyz,
            const float* __restrict__ centers,
            const int*   __restrict__ idx,
            const float* __restrict__ W1, const float* __restrict__ b1,
            const float* __restrict__ W2, const float* __restrict__ b2,
            const float* __restrict__ W3, const float* __restrict__ b3,
            float* __restrict__ out) {
    extern __shared__ uint32_t smw[];
    uint32_t* h1u = smw;                     // [256][S1W] f16x2
    uint32_t* h2u = smw + H1W;               // [256][S2W]

    __shared__ float4 wb1[64];               // {w0,w1,w2,bias}

    const int tid  = threadIdx.x;
    const int warp = tid >> 5;               // 0..7
    const int lane = tid & 31;
    const int g    = lane >> 2;
    const int t    = lane & 3;

    const uint32_t h1a = smem_u32(h1u);
    const uint32_t h2a = smem_u32(h2u);
    const uint32_t lm1 = h1a + (uint32_t)(lane & 15) * S1B + (uint32_t)(lane >> 4) * 16;
    const uint32_t lm2 = h2a + (uint32_t)(lane & 15) * S2B + (uint32_t)(lane >> 4) * 16;

    // ---- one-time: W1/b1 table ----
    if (tid < 64)
        wb1[tid] = make_float4(__ldg(&W1[tid * 3 + 0]), __ldg(&W1[tid * 3 + 1]),
                               __ldg(&W1[tid * 3 + 2]), __ldg(&b1[tid]));

    // ---- one-time: resident f16 W3 fragments (the big, reused array) ----
    const int chb = warp * 32;               // GEMM3 n-strip (32 ch)
    uint32_t b3f[8][4][2];
#pragma unroll
    for (int kc = 0; kc < 8; kc++)
#pragma unroll
        for (int n = 0; n < 4; n++) {
            const int row = chb + n * 8 + g;
            const float* wr = W3 + (size_t)row * C2 + kc * 16;
            b3f[kc][n][0] = packh2(__ldg(wr + 2 * t),     __ldg(wr + 2 * t + 1));
            b3f[kc][n][1] = packh2(__ldg(wr + 2 * t + 8), __ldg(wr + 2 * t + 9));
        }
    const int c2b = warp * 16;               // GEMM2 n-strip (16 c2)
    float b3r[4][2];
#pragma unroll
    for (int n = 0; n < 4; n++) {
        const int ch = chb + n * 8 + 2 * (lane & 3);
        b3r[n][0] = __ldg(&b3[ch]);
        b3r[n][1] = __ldg(&b3[ch + 1]);
    }

    __syncthreads();                         // wb1 visible before any layer1

    auto gather = [&](int grp, float& lx, float& ly, float& lz) {
        const int bm0 = grp * P;
        const int b   = bm0 >> 11;
        const int bm  = bm0 + (tid >> 5);
        const int id  = __ldg(&idx[(size_t)bm * Kn + (tid & 31)]);
        const float* xp = xyz + ((size_t)b * Nn + id) * 3;
        const float* cp = centers + (size_t)bm * 3;
        lx = __ldg(xp + 0) - __ldg(cp + 0);
        ly = __ldg(xp + 1) - __ldg(cp + 1);
        lz = __ldg(xp + 2) - __ldg(cp + 2);
    };
    auto layer1 = [&](float lx, float ly, float lz) {
        uint32_t* ph = h1u + tid * S1W;
#pragma unroll
        for (int j4 = 0; j4 < 8; j4++) {
            uint4 o;
#pragma unroll
            for (int w = 0; w < 4; w++) {
                const int c0 = j4 * 8 + 2 * w;
                const float4 wa = wb1[c0];
                const float4 wb = wb1[c0 + 1];
                const float vlo = fmaxf(fmaf(wa.x, lx, fmaf(wa.y, ly, fmaf(wa.z, lz, wa.w))), 0.f);
                const float vhi = fmaxf(fmaf(wb.x, lx, fmaf(wb.y, ly, fmaf(wb.z, lz, wb.w))), 0.f);
                (&o.x)[w] = packh2(vlo, vhi);
            }
            *reinterpret_cast<uint4*>(ph + j4 * 4) = o;
        }
    };

    // ---- prologue ----
    int grp = blockIdx.x;
    if (grp < NGRP) {
        float lx, ly, lz;
        gather(grp, lx, ly, lz);
        layer1(lx, ly, lz);
    }
    __syncthreads();

    // ---- persistent group loop ----
    for (; grp < NGRP; grp += GRID) {
        const int bm0 = grp * P;

        float nlx = 0.f, nly = 0.f, nlz = 0.f;
        {
            int gn = grp + GRID;
            if (gn >= NGRP) gn = NGRP - 1;
            gather(gn, nlx, nly, nlz);
        }

        // per-group b2f/bias2 load (L1-hot; keeps the register peak low —
        // b2f is dead during GEMM3 so it shouldn't stay resident)
        uint32_t b2f[4][2][2];
#pragma unroll
        for (int kc = 0; kc < 4; kc++)
#pragma unroll
            for (int n = 0; n < 2; n++) {
                const int row = c2b + n * 8 + g;
                const float* wr = W2 + (size_t)row * C1 + kc * 16;
                b2f[kc][n][0] = packh2(__ldg(wr + 2 * t),     __ldg(wr + 2 * t + 1));
                b2f[kc][n][1] = packh2(__ldg(wr + 2 * t + 8), __ldg(wr + 2 * t + 9));
            }
        const float bias2a = __ldg(&b2[c2b + 2 * t]);
        const float bias2b = __ldg(&b2[c2b + 2 * t + 1]);

        // -- GEMM2: 4 passes of M=64; 16 pipelined (mt,kc) steps each --
#pragma unroll 1
        for (int pass = 0; pass < 4; pass++) {
            const uint32_t base = lm1 + (uint32_t)(pass * 64) * S1B;
            float acc[4][2][4];
#pragma unroll
            for (int mt = 0; mt < 4; mt++)
#pragma unroll
                for (int n = 0; n < 2; n++)
#pragma unroll
                    for (int i = 0; i < 4; i++) acc[mt][n][i] = 0.f;

            uint4 fr[2];
            ldsm4(fr[0], base);
#pragma unroll
            for (int s = 0; s < 16; s++) {
                const int mt = s >> 2, kc = s & 3;
                if (s + 1 < 16) {
                    const int s1 = s + 1;
                    ldsm4(fr[s1 & 1], base + (uint32_t)((s1 >> 2) * 16 * S1B + (s1 & 3) * 32));
                }
                const uint4 a = fr[s & 1];
#pragma unroll
                for (int n = 0; n < 2; n++)
                    mma16(acc[mt][n][0], acc[mt][n][1], acc[mt][n][2], acc[mt][n][3],
                          a.x, a.y, a.z, a.w, b2f[kc][n][0], b2f[kc][n][1]);
            }
            // epi2: +bias, relu, pack, store (word cols warp*8 + n*4 + t)
#pragma unroll
            for (int mt = 0; mt < 4; mt++) {
                const int r0 = pass * 64 + mt * 16 + g;
#pragma unroll
                for (int n = 0; n < 2; n++) {
                    const int wcol = warp * 8 + n * 4 + t;
                    h2u[r0 * S2W + wcol] =
                        packh2(fmaxf(acc[mt][n][0] + bias2a, 0.f),
                               fmaxf(acc[mt][n][1] + bias2b, 0.f));
                    h2u[(r0 + 8) * S2W + wcol] =
                        packh2(fmaxf(acc[mt][n][2] + bias2a, 0.f),
                               fmaxf(acc[mt][n][3] + bias2b, 0.f));
                }
            }
        }
        __syncthreads();

        // -- GEMM3 + max epilogue: per p, 16 pipelined (hmt,kc) steps --
#pragma unroll 1
        for (int p = 0; p < P; p++) {
            const uint32_t base = lm2 + (uint32_t)(p * 32) * S2B;
            float acc[2][4][4];
#pragma unroll
            for (int h = 0; h < 2; h++)
#pragma unroll
                for (int n = 0; n < 4; n++)
#pragma unroll
                    for (int i = 0; i < 4; i++) acc[h][n][i] = 0.f;

            uint4 fr[2];
            ldsm4(fr[0], base);
#pragma unroll
            for (int s = 0; s < 16; s++) {
                const int hmt = s >> 3, kc = s & 7;
                if (s + 1 < 16) {
                    const int s1 = s + 1;
                    ldsm4(fr[s1 & 1], base + (uint32_t)((s1 >> 3) * 16 * S2B + (s1 & 7) * 32));
                }
                const uint4 a = fr[s & 1];
#pragma unroll
                for (int n = 0; n < 4; n++)
                    mma16(acc[hmt][n][0], acc[hmt][n][1], acc[hmt][n][2], acc[hmt][n][3],
                          a.x, a.y, a.z, a.w, b3f[kc][n][0], b3f[kc][n][1]);
            }

#pragma unroll
            for (int n = 0; n < 4; n++) {
                float ve = fmaxf(fmaxf(acc[0][n][0], acc[0][n][2]),
                                 fmaxf(acc[1][n][0], acc[1][n][2]));
                float vo = fmaxf(fmaxf(acc[0][n][1], acc[0][n][3]),
                                 fmaxf(acc[1][n][1], acc[1][n][3]));
#pragma unroll
                for (int s = 4; s < 32; s <<= 1) {
                    ve = fmaxf(ve, __shfl_xor_sync(0xffffffffu, ve, s));
                    vo = fmaxf(vo, __shfl_xor_sync(0xffffffffu, vo, s));
                }
                if (lane < 4) {
                    const int ch = chb + n * 8 + 2 * lane;
                    float2 o = {ve + b3r[n][0], vo + b3r[n][1]};
                    *reinterpret_cast<float2*>(out + (size_t)(bm0 + p) * C3 + ch) = o;
                }
            }
        }

        // -- layer1 for next group --
        layer1(nlx, nly, nlz);
        __syncthreads();
    }
}

extern "C" void kernel_launch(void* const* d_in, const int* in_sizes, int n_in,
                              void* d_out, int out_size) {
    (void)in_sizes; (void)n_in; (void)out_size;
    const float* xyz     = (const float*)d_in[0];
    const float* centers = (const float*)d_in[1];
    const int*   idx     = (const int*)  d_in[2];
    const float* W1      = (const float*)d_in[3];
    const float* b1      = (const float*)d_in[4];
    const float* W2      = (const float*)d_in[5];
    const float* b2      = (const float*)d_in[6];
    const float* W3      = (const float*)d_in[7];
    const float* b3      = (const float*)d_in[8];
    float*       out     = (float*)d_out;

    cudaFuncSetAttribute(pe_mma, cudaFuncAttributeMaxDynamicSharedMemorySize, SMEM_BYTES);
    pe_mma<<<GRID, THREADS, SMEM_BYTES>>>(xyz, centers, idx,
                                          W1, b1, W2, b2, W3, b3, out);
}